// round 8
// baseline (speedup 1.0000x reference)
#include <cuda_runtime.h>
#include <math.h>

#define DEPTH 2
#define NQ 4
#define M_CH 512
#define B_SZ 128
#define NSL 8              // 4-row slices per image

// Pooling partials: [b][slice][side][m] -> 128*8*2*512 floats = 2 MB (L2-resident)
__device__ float g_part[B_SZ * NSL * 2 * M_CH];
// Per-batch completion counters (self-resetting each launch; BSS zero-init)
__device__ int g_cnt[B_SZ];

__device__ __forceinline__ float fast_tanh(float x) {
    return __fdividef(2.f, 1.f + __expf(-2.f * x)) - 1.f;
}

// Fused kernel: CTA = (b, 4-row slice). Streams + reduces its slice; the 8th
// CTA to finish a batch b runs the 4-qubit sim for all 512 channels of b.
__global__ __launch_bounds__(512, 2) void fused_kernel(const float* __restrict__ in,
                                                       const float* __restrict__ w,
                                                       float* __restrict__ out) {
    const int bid = blockIdx.x;            // 0..1023
    const int t   = threadIdx.x;           // 0..511
    const int b     = bid >> 3;
    const int slice = bid & (NSL - 1);
    const int rs    = t >> 7;              // row within slice (0..3)
    const int m4    = t & 127;             // channel group (4 channels)
    const int row   = slice * 4 + rs;

    // ---- streaming pool: 32 independent float4 evict-first loads ----
    const float4* rp = (const float4*)in
                     + ((size_t)b * 1024 + (size_t)row * 32) * 128 + m4;
    float4 sL = make_float4(0.f, 0.f, 0.f, 0.f);
    float4 sR = make_float4(0.f, 0.f, 0.f, 0.f);
    #pragma unroll
    for (int c = 0; c < 16; c++) {
        float4 v = __ldcs(rp + c * 128);
        sL.x += v.x; sL.y += v.y; sL.z += v.z; sL.w += v.w;
    }
    #pragma unroll
    for (int c = 16; c < 32; c++) {
        float4 v = __ldcs(rp + c * 128);
        sR.x += v.x; sR.y += v.y; sR.z += v.z; sR.w += v.w;
    }

    // ---- in-CTA reduction over the 4 rows ----
    __shared__ float4 red[512 * 2];
    red[t * 2]     = sL;
    red[t * 2 + 1] = sR;
    __syncthreads();
    if (t < 256) {
        float4 a = red[t * 2],     b4 = red[(t + 256) * 2];
        float4 c = red[t * 2 + 1], d4 = red[(t + 256) * 2 + 1];
        a.x += b4.x; a.y += b4.y; a.z += b4.z; a.w += b4.w;
        c.x += d4.x; c.y += d4.y; c.z += d4.z; c.w += d4.w;
        red[t * 2]     = a;
        red[t * 2 + 1] = c;
    }
    __syncthreads();
    if (t < 128) {
        float4 a = red[t * 2],     b4 = red[(t + 128) * 2];
        float4 c = red[t * 2 + 1], d4 = red[(t + 128) * 2 + 1];
        a.x += b4.x; a.y += b4.y; a.z += b4.z; a.w += b4.w;
        c.x += d4.x; c.y += d4.y; c.z += d4.z; c.w += d4.w;
        float4* p = (float4*)g_part + ((size_t)(b * NSL + slice) * 2) * 128 + t;
        p[0]   = a;      // side L
        p[128] = c;      // side R
        __threadfence();   // release partials before the count
    }
    __syncthreads();

    // ---- last-CTA election for batch b ----
    __shared__ int s_last;
    if (t == 0) {
        int old = atomicAdd(&g_cnt[b], 1);
        s_last = (old == NSL - 1);
        if (old == NSL - 1) g_cnt[b] = 0;   // self-reset for next graph replay
    }
    __syncthreads();
    if (!s_last) return;
    __threadfence();   // acquire: partials from the other 7 CTAs

    // =================== sim for batch b, thread t = channel m ===================
    const int m = t;
    const float* p = g_part + (size_t)b * (NSL * 2 * M_CH) + m;
    float v[16];
    #pragma unroll
    for (int s = 0; s < 16; s++) v[s] = p[s * M_CH];
    float a00 = 0.f, a01 = 0.f, a10 = 0.f, a11 = 0.f;
    #pragma unroll
    for (int s = 0; s < 4; s++) { a00 += v[s * 2]; a01 += v[s * 2 + 1]; }
    #pragma unroll
    for (int s = 4; s < 8; s++) { a10 += v[s * 2]; a11 += v[s * 2 + 1]; }

    const float PI = 3.14159265358979f;
    const float inv = 1.f / 256.f;
    float ang0 = fast_tanh(a00 * inv) * PI;
    float ang1 = fast_tanh(a01 * inv) * PI;
    float ang2 = fast_tanh(a10 * inv) * PI;
    float ang3 = fast_tanh(a11 * inv) * PI;

    float s0, c0, s1, c1, s2, c2, s3, c3;
    __sincosf(0.5f * ang0, &s0, &c0);   // |arg| <= pi/2
    __sincosf(0.5f * ang1, &s1, &c1);
    __sincosf(0.5f * ang2, &s2, &c2);
    __sincosf(0.5f * ang3, &s3, &c3);

    float re[16], im[16];
    {
        float p0[2] = {c0, s0}, p1[2] = {c1, s1}, p2_[2] = {c2, s2}, p3[2] = {c3, s3};
        #pragma unroll
        for (int x = 0; x < 16; x++) {
            re[x] = p0[(x >> 3) & 1] * p1[(x >> 2) & 1] * p2_[(x >> 1) & 1] * p3[x & 1];
            im[x] = 0.f;
        }
    }

    // 6-CNOT cascade composed: (a,b,c,d) -> (a, a^b, b^c, c^d); new[PERM[x]] = old[x]
    const int PERM[16] = {0, 1, 3, 2, 6, 7, 5, 4, 12, 13, 15, 14, 10, 11, 9, 8};

    const float* wm = w + m * (DEPTH * NQ * 3);   // weights for this channel (L1-hot)

    #pragma unroll
    for (int step = 0; step < DEPTH * NQ; step++) {
        const int q = step & 3;
        // build Rot gate for (layer, q, m) in registers
        const float* wp = wm + step * 3;
        float phi = wp[0], theta = wp[1], omega = wp[2];
        float st, ct; sincosf(0.5f * theta,         &st, &ct);
        float sp, cp; sincosf(0.5f * (phi + omega), &sp, &cp);
        float sm, cm; sincosf(0.5f * (phi - omega), &sm, &cm);
        float gAx =  cp * ct, gAy = -sp * ct;   // g00
        float gAz = -cm * st, gAw = -sm * st;   // g01
        float gBx =  cm * st, gBy = -sm * st;   // g10
        float gBz =  cp * ct, gBw =  sp * ct;   // g11

        const int mask = 8 >> q;
        #pragma unroll
        for (int i = 0; i < 16; i++) {
            if (i & mask) continue;
            const int j = i | mask;
            float ar = re[i], ai = im[i], br = re[j], bi = im[j];
            re[i] = gAx * ar - gAy * ai + gAz * br - gAw * bi;
            im[i] = gAx * ai + gAy * ar + gAz * bi + gAw * br;
            re[j] = gBx * ar - gBy * ai + gBz * br - gBw * bi;
            im[j] = gBx * ai + gBy * ar + gBz * bi + gBw * br;
        }
        if (q == 3) {
            float tr[16], ti[16];
            #pragma unroll
            for (int x = 0; x < 16; x++) { tr[PERM[x]] = re[x]; ti[PERM[x]] = im[x]; }
            #pragma unroll
            for (int x = 0; x < 16; x++) { re[x] = tr[x]; im[x] = ti[x]; }
        }
    }

    float z = 0.f;
    #pragma unroll
    for (int x = 0; x < 8; x++)  z += re[x] * re[x] + im[x] * im[x];
    #pragma unroll
    for (int x = 8; x < 16; x++) z -= re[x] * re[x] + im[x] * im[x];

    out[(size_t)b * M_CH + m] = z;
}

extern "C" void kernel_launch(void* const* d_in, const int* in_sizes, int n_in,
                              void* d_out, int out_size) {
    const float* in = (const float*)d_in[0];
    const float* w  = (const float*)d_in[1];
    if (n_in >= 2 && in_sizes[0] < in_sizes[1]) {
        const float* t = in; in = w; w = t;
    }
    fused_kernel<<<B_SZ * NSL, 512>>>(in, w, (float*)d_out);
}

// round 9
// speedup vs baseline: 1.0416x; 1.0416x over previous
#include <cuda_runtime.h>
#include <math.h>

#define DEPTH 2
#define NQ 4
#define M_CH 512
#define B_SZ 128
#define NSL 8              // 4-row slices per image

// Pooling partials: [b][slice][side][m] -> 128*8*2*512 floats = 2 MB (L2-resident)
__device__ float g_part[B_SZ * NSL * 2 * M_CH];

// ---- Kernel P: streaming pool (identical to the proven R7 version, gates branch removed).
__global__ __launch_bounds__(512) void pool_kernel(const float* __restrict__ in) {
    const int bid = blockIdx.x;            // 0..1023
    const int t   = threadIdx.x;           // 0..511
    const int b     = bid >> 3;
    const int slice = bid & (NSL - 1);
    const int rs    = t >> 7;              // row within slice (0..3)
    const int m4    = t & 127;             // channel group (4 channels)
    const int row   = slice * 4 + rs;

    const float4* rp = (const float4*)in
                     + ((size_t)b * 1024 + (size_t)row * 32) * 128 + m4;
    float4 sL = make_float4(0.f, 0.f, 0.f, 0.f);
    float4 sR = make_float4(0.f, 0.f, 0.f, 0.f);
    #pragma unroll
    for (int c = 0; c < 16; c++) {
        float4 v = __ldcs(rp + c * 128);
        sL.x += v.x; sL.y += v.y; sL.z += v.z; sL.w += v.w;
    }
    #pragma unroll
    for (int c = 16; c < 32; c++) {
        float4 v = __ldcs(rp + c * 128);
        sR.x += v.x; sR.y += v.y; sR.z += v.z; sR.w += v.w;
    }

    __shared__ float4 red[512 * 2];
    red[t * 2]     = sL;
    red[t * 2 + 1] = sR;
    __syncthreads();
    if (t < 256) {
        float4 a = red[t * 2],     b4 = red[(t + 256) * 2];
        float4 c = red[t * 2 + 1], d4 = red[(t + 256) * 2 + 1];
        a.x += b4.x; a.y += b4.y; a.z += b4.z; a.w += b4.w;
        c.x += d4.x; c.y += d4.y; c.z += d4.z; c.w += d4.w;
        red[t * 2]     = a;
        red[t * 2 + 1] = c;
    }
    __syncthreads();
    if (t < 128) {
        float4 a = red[t * 2],     b4 = red[(t + 128) * 2];
        float4 c = red[t * 2 + 1], d4 = red[(t + 128) * 2 + 1];
        a.x += b4.x; a.y += b4.y; a.z += b4.z; a.w += b4.w;
        c.x += d4.x; c.y += d4.y; c.z += d4.z; c.w += d4.w;
        float4* p = (float4*)g_part + ((size_t)(b * NSL + slice) * 2) * 128 + t;
        p[0]   = a;      // side L
        p[128] = c;      // side R
    }
}

__device__ __forceinline__ float fast_tanh(float x) {
    return __fdividef(2.f, 1.f + __expf(-2.f * x)) - 1.f;
}

// ---- Kernel S: CTA per channel-group g (4 channels). Builds U_m columns,
//      assembles M_m = Re(U† Z0 U) in smem, then thread (ml,b) evaluates the
//      quadratic form z = psi0^T M psi0.
__global__ __launch_bounds__(512) void sim_kernel(const float* __restrict__ w,
                                                  float* __restrict__ out) {
    const int g = blockIdx.x;              // 0..127 channel group
    const int t = threadIdx.x;             // 0..511

    // padded smem
    __shared__ float h[B_SZ * 33];         // per-b quadrant partials (pitch 33)
    __shared__ float ur[4 * 16 * 17];      // UR[ml][x][j], pitch 17
    __shared__ float ui[4 * 16 * 17];
    __shared__ float Ms[4 * 16 * 17];      // M[ml][i][j], pitch 17 rows

    // ---- Phase A: stage partials (column g of p4) and pre-reduce to h ----
    // global float4 index = k*128 + g, k = b*16 + slice*2 + side in [0,2048)
    {
        const int b = t >> 2;              // 0..127
        const int j = t & 3;               // k-block (4 consecutive k)
        const float4* p4 = (const float4*)g_part;
        float4 v0 = __ldg(p4 + (size_t)(t * 4 + 0) * 128 + g);
        float4 v1 = __ldg(p4 + (size_t)(t * 4 + 1) * 128 + g);
        float4 v2 = __ldg(p4 + (size_t)(t * 4 + 2) * 128 + g);
        float4 v3 = __ldg(p4 + (size_t)(t * 4 + 3) * 128 + g);
        // k = t*4+i : (slice = k>>1 & 7 within b, side = k&1). Within this thread:
        // i=0:(s,L) i=1:(s,R) i=2:(s+1,L) i=3:(s+1,R)
        float4 sL = make_float4(v0.x + v2.x, v0.y + v2.y, v0.z + v2.z, v0.w + v2.w);
        float4 sR = make_float4(v1.x + v3.x, v1.y + v3.y, v1.z + v3.z, v1.w + v3.w);
        float* hb = h + b * 33 + j * 8;
        hb[0] = sL.x; hb[1] = sL.y; hb[2] = sL.z; hb[3] = sL.w;
        hb[4] = sR.x; hb[5] = sR.y; hb[6] = sR.z; hb[7] = sR.w;
    }

    // ---- Phase B: evolve 16 basis columns per channel (threads 0..63) ----
    if (t < 64) {
        const int ml = t >> 4;             // 0..3
        const int j  = t & 15;             // basis column
        const int m  = g * 4 + ml;

        float re[16], im[16];
        #pragma unroll
        for (int x = 0; x < 16; x++) { re[x] = (x == j) ? 1.f : 0.f; im[x] = 0.f; }

        const int PERM[16] = {0, 1, 3, 2, 6, 7, 5, 4, 12, 13, 15, 14, 10, 11, 9, 8};
        const float* wm = w + m * (DEPTH * NQ * 3);

        #pragma unroll
        for (int step = 0; step < DEPTH * NQ; step++) {
            const int q = step & 3;
            const float* wp = wm + step * 3;
            float phi = wp[0], theta = wp[1], omega = wp[2];
            float st, ct; sincosf(0.5f * theta,         &st, &ct);
            float sp, cp; sincosf(0.5f * (phi + omega), &sp, &cp);
            float sm, cm; sincosf(0.5f * (phi - omega), &sm, &cm);
            float gAx =  cp * ct, gAy = -sp * ct;   // g00
            float gAz = -cm * st, gAw = -sm * st;   // g01
            float gBx =  cm * st, gBy = -sm * st;   // g10
            float gBz =  cp * ct, gBw =  sp * ct;   // g11

            const int mask = 8 >> q;
            #pragma unroll
            for (int i = 0; i < 16; i++) {
                if (i & mask) continue;
                const int jj = i | mask;
                float ar = re[i], ai = im[i], br = re[jj], bi = im[jj];
                re[i]  = gAx * ar - gAy * ai + gAz * br - gAw * bi;
                im[i]  = gAx * ai + gAy * ar + gAz * bi + gAw * br;
                re[jj] = gBx * ar - gBy * ai + gBz * br - gBw * bi;
                im[jj] = gBx * ai + gBy * ar + gBz * bi + gBw * br;
            }
            if (q == 3) {
                float tr[16], ti[16];
                #pragma unroll
                for (int x = 0; x < 16; x++) { tr[PERM[x]] = re[x]; ti[PERM[x]] = im[x]; }
                #pragma unroll
                for (int x = 0; x < 16; x++) { re[x] = tr[x]; im[x] = ti[x]; }
            }
        }
        #pragma unroll
        for (int x = 0; x < 16; x++) {
            ur[ml * 272 + x * 17 + j] = re[x];
            ui[ml * 272 + x * 17 + j] = im[x];
        }
    }
    __syncthreads();

    // ---- Phase C: M[ml][i][j] = sum_x s_x (UR_xi UR_xj + UI_xi UI_xj) ----
    #pragma unroll
    for (int e = t; e < 1024; e += 512) {
        const int ml = e >> 8;
        const int i  = (e >> 4) & 15;
        const int jj = e & 15;
        const float* urm = ur + ml * 272;
        const float* uim = ui + ml * 272;
        float acc = 0.f;
        #pragma unroll
        for (int x = 0; x < 8; x++)
            acc += urm[x * 17 + i] * urm[x * 17 + jj] + uim[x * 17 + i] * uim[x * 17 + jj];
        #pragma unroll
        for (int x = 8; x < 16; x++)
            acc -= urm[x * 17 + i] * urm[x * 17 + jj] + uim[x * 17 + i] * uim[x * 17 + jj];
        Ms[ml * 272 + i * 17 + jj] = acc;
    }
    __syncthreads();

    // ---- Phase D: quadratic form per (ml, b) ----
    {
        const int ml = t >> 7;             // 0..3
        const int b  = t & 127;            // 0..127
        const float* hb = h + b * 33;
        // quadrants: top = j-blocks 0,1 ; bottom = 2,3 ; side L=+0, R=+4
        float a00 = hb[0 * 8 + 0 + ml] + hb[1 * 8 + 0 + ml];
        float a01 = hb[0 * 8 + 4 + ml] + hb[1 * 8 + 4 + ml];
        float a10 = hb[2 * 8 + 0 + ml] + hb[3 * 8 + 0 + ml];
        float a11 = hb[2 * 8 + 4 + ml] + hb[3 * 8 + 4 + ml];

        const float PI = 3.14159265358979f;
        const float inv = 1.f / 256.f;
        float ang0 = fast_tanh(a00 * inv) * PI;
        float ang1 = fast_tanh(a01 * inv) * PI;
        float ang2 = fast_tanh(a10 * inv) * PI;
        float ang3 = fast_tanh(a11 * inv) * PI;

        float s0, c0, s1, c1, s2, c2, s3, c3;
        __sincosf(0.5f * ang0, &s0, &c0);   // |arg| <= pi/2
        __sincosf(0.5f * ang1, &s1, &c1);
        __sincosf(0.5f * ang2, &s2, &c2);
        __sincosf(0.5f * ang3, &s3, &c3);

        float psi[16];
        {
            float p0[2] = {c0, s0}, p1[2] = {c1, s1}, p2_[2] = {c2, s2}, p3[2] = {c3, s3};
            #pragma unroll
            for (int x = 0; x < 16; x++)
                psi[x] = p0[(x >> 3) & 1] * p1[(x >> 2) & 1] * p2_[(x >> 1) & 1] * p3[x & 1];
        }

        const float* Mm = Ms + ml * 272;
        float z = 0.f;
        #pragma unroll
        for (int i = 0; i < 16; i++) {
            float inner = 0.f;
            #pragma unroll
            for (int jj = 0; jj < 16; jj++) inner += Mm[i * 17 + jj] * psi[jj];
            z += psi[i] * inner;
        }
        out[(size_t)b * M_CH + g * 4 + ml] = z;
    }
}

extern "C" void kernel_launch(void* const* d_in, const int* in_sizes, int n_in,
                              void* d_out, int out_size) {
    const float* in = (const float*)d_in[0];
    const float* w  = (const float*)d_in[1];
    if (n_in >= 2 && in_sizes[0] < in_sizes[1]) {
        const float* t = in; in = w; w = t;
    }
    pool_kernel<<<B_SZ * NSL, 512>>>(in);
    sim_kernel<<<128, 512>>>(w, (float*)d_out);
}